// round 8
// baseline (speedup 1.0000x reference)
#include <cuda_runtime.h>
#include <math.h>

#define T_LEN    176400
#define NBATCH   16
#define NHARM    64
#define NBANDS   65
#define MAIN_NB  690          // ceil(176400/256)
#define NORM_BPR 87           // 87*512 = 44544 >= 44100 float4 per row
#define PI_D 3.141592653589793115997963468544185161590576171875

// Scratch (no allocations allowed). Transposed layout [batch][block]:
// norm's reduce reads are coalesced. Every slot overwritten by plain stores
// each call before being read -> no reset needed, replay-deterministic.
__device__ float g_partial[NBATCH * MAIN_NB];

// ---------------------------------------------------------------------------
// Range reduction, bit-exact w.r.t. the reference's f32 argument:
//  n = RNE(arg/2pi) via 1.5*2^23 magic; 2-term Cody-Waite -> r in [-pi,pi].
// Then __sinf(r): RRO+MUFU, documented abs err 2^-21.4 on [-pi,pi] — runs on
// the MUFU pipe, freeing the fma pipe (was an 8-op Taylor tail).
// ---------------------------------------------------------------------------
__device__ __forceinline__ float sin_reduced(float a) {
    const float I2PI  = 0.15915494309189535f;
    const float MAGIC = 12582912.0f;                // 1.5 * 2^23
    const float C1    = 6.28318548202514648437500f; // fl32(2*pi)
    const float C2N   = 1.7484556000744625e-7f;     // -(2*pi - C1)
    float t  = fmaf(a, I2PI, MAGIC);
    float nf = t - MAGIC;                           // RNE(a/2pi), exact int
    float r  = fmaf(nf, -C1, a);
    r = fmaf(nf, C2N, r);                           // r in ~[-pi, pi]
    return __sinf(r);                               // MUFU pipe
}

// ---------------------------------------------------------------------------
// Main kernel: one thread = one time sample, all 16 batches. k-loop fully
// unrolled: ck = fl32(C32*(k+1)) constant-folds to an immediate per iter,
// preserving the reference's rounding (compile-time IEEE f32 RN).
// Block-level |max| per batch -> plain store to g_partial (no atomics).
// ---------------------------------------------------------------------------
__global__ void __launch_bounds__(256, 4) ddsp_main(
    const float* __restrict__ hd,      // (16, 64)
    const float* __restrict__ nbands,  // (16, 65)
    const float* __restrict__ adsr,    // (16, 4)
    const float* __restrict__ gain,    // (16, 1)
    const float* __restrict__ noise,   // (16, T)
    float* __restrict__ out)           // (16, T)
{
    __shared__ float sh_hd[NHARM * 16];   // transposed: [k][b]
    __shared__ float sh_par[NBATCH * 12];
    __shared__ unsigned int sh_max[NBATCH];

    int tid = threadIdx.x;
    for (int idx = tid; idx < NHARM * 16; idx += 256) {
        int k = idx >> 4, b = idx & 15;
        sh_hd[idx] = hd[b * NHARM + k];
    }
    if (tid < NBATCH) {
        int b = tid;
        sh_max[b] = 0u;

        float s = 0.0f;
        for (int j = 0; j < NBANDS; j++) s += nbands[b * NBANDS + j];
        float nl = (s / (float)NBANDS) * 0.1f;

        float attack  = adsr[b * 4 + 0];
        float decay   = adsr[b * 4 + 1];
        float sus     = adsr[b * 4 + 2];
        float release = adsr[b * 4 + 3];

        int a  = (int)floorf(__fmul_rn(__fmul_rn(attack,  0.5f), 44100.0f)) + 1;
        int dd = (int)floorf(__fmul_rn(__fmul_rn(decay,   0.5f), 44100.0f)) + 1;
        int rr = (int)floorf(__fmul_rn(__fmul_rn(release, 0.5f), 44100.0f)) + 1;
        int total = a + dd + rr;
        if (total > T_LEN) {
            float scale = __fdiv_rn((float)T_LEN, (float)total);
            a  = (int)floorf(__fmul_rn((float)a,  scale));
            dd = (int)floorf(__fmul_rn((float)dd, scale));
            rr = (int)floorf(__fmul_rn((float)rr, scale));
        }
        int ss = T_LEN - (a + dd + rr);
        if (ss < 0) ss = 0;

        float af = (float)a, df = (float)dd, sf = (float)ss, rf = (float)rr;
        float* P = sh_par + b * 12;
        P[0] = af;
        P[1] = af + df;
        P[2] = af + df + sf;
        P[3] = 1.0f / fmaxf(af - 1.0f, 1.0f);
        P[4] = 1.0f / fmaxf(df - 1.0f, 1.0f);
        P[5] = 1.0f / fmaxf(rf - 1.0f, 1.0f);
        P[6] = sus;
        P[7] = gain[b];
        P[8] = nl;
    }
    __syncthreads();

    int i = blockIdx.x * 256 + tid;
    bool act = (i < T_LEN);
    float fi = (float)i;
    const float DELTA = 4.0f / 176399.0f;         // compile-time IEEE f32
    float ti = __fmul_rn(fi, DELTA);              // jax linspace: iota*delta

    float acc[16];
#pragma unroll
    for (int b = 0; b < 16; b++) acc[b] = 0.0f;

    const float C32 = (float)(2.0 * PI_D * 440.0);  // fl32(2*pi*440)
#pragma unroll
    for (int k = 0; k < NHARM; k++) {
        float ck = C32 * (float)(k + 1);            // constant-folded fl32
        float sv = sin_reduced(__fmul_rn(ck, ti));  // matches ref f32 rounding
        const float4* hp = (const float4*)(sh_hd + k * 16);
        float4 h0 = hp[0], h1 = hp[1], h2 = hp[2], h3 = hp[3];
        acc[0]  = fmaf(h0.x, sv, acc[0]);  acc[1]  = fmaf(h0.y, sv, acc[1]);
        acc[2]  = fmaf(h0.z, sv, acc[2]);  acc[3]  = fmaf(h0.w, sv, acc[3]);
        acc[4]  = fmaf(h1.x, sv, acc[4]);  acc[5]  = fmaf(h1.y, sv, acc[5]);
        acc[6]  = fmaf(h1.z, sv, acc[6]);  acc[7]  = fmaf(h1.w, sv, acc[7]);
        acc[8]  = fmaf(h2.x, sv, acc[8]);  acc[9]  = fmaf(h2.y, sv, acc[9]);
        acc[10] = fmaf(h2.z, sv, acc[10]); acc[11] = fmaf(h2.w, sv, acc[11]);
        acc[12] = fmaf(h3.x, sv, acc[12]); acc[13] = fmaf(h3.y, sv, acc[13]);
        acc[14] = fmaf(h3.z, sv, acc[14]); acc[15] = fmaf(h3.w, sv, acc[15]);
    }

    const unsigned full = 0xFFFFFFFFu;
#pragma unroll
    for (int b = 0; b < 16; b++) {
        const float* P = sh_par + b * 12;
        float af = P[0], afd = P[1], ads = P[2];
        float ida = P[3], idd = P[4], idr = P[5];
        float sus = P[6], gn = P[7], nl = P[8];

        float env;
        if (fi < af)       env = fi * ida;
        else if (fi < afd) env = 1.0f + ((sus - 1.0f) * (fi - af)) * idd;
        else if (fi < ads) env = sus;
        else               env = sus * (1.0f - (fi - ads) * idr);

        float nz = act ? noise[b * T_LEN + i] : 0.0f;
        float nn = fmaf(nz, 2.0f, -1.0f) * nl;
        float sig = ((acc[b] + nn) * env) * gn;
        if (!act) sig = 0.0f;
        if (act) out[b * T_LEN + i] = sig;

        float am = fabsf(sig);
#pragma unroll
        for (int off = 16; off; off >>= 1)
            am = fmaxf(am, __shfl_xor_sync(full, am, off));
        if ((tid & 31) == 0) atomicMax(&sh_max[b], __float_as_uint(am));
    }
    __syncthreads();
    // plain stores — transposed [batch][block] slots, overwritten every call
    if (tid < NBATCH)
        g_partial[tid * MAIN_NB + blockIdx.x] = __uint_as_float(sh_max[tid]);
}

// ---------------------------------------------------------------------------
// Norm kernel: block (x, b) redundantly reduces batch b's 690 partials
// (contiguous/coalesced now: 2.8KB per row, L2-resident), then scales its
// 2-float4 chunk of row b in place. No atomics, no inter-block sync.
// ---------------------------------------------------------------------------
__global__ void __launch_bounds__(256) ddsp_norm(float4* __restrict__ out) {
    __shared__ float sh_wmax[8];
    __shared__ float sh_inv;
    const int T4 = T_LEN / 4;                 // 44100 float4 per row
    int b = blockIdx.y;
    int tid = threadIdx.x;

    // reduce 690 contiguous partials for batch b
    const float* part = g_partial + b * MAIN_NB;
    float m = 0.0f;
    for (int j = tid; j < MAIN_NB; j += 256)
        m = fmaxf(m, part[j]);
    const unsigned full = 0xFFFFFFFFu;
#pragma unroll
    for (int off = 16; off; off >>= 1)
        m = fmaxf(m, __shfl_xor_sync(full, m, off));
    if ((tid & 31) == 0) sh_wmax[tid >> 5] = m;
    __syncthreads();
    if (tid == 0) {
        float mm = sh_wmax[0];
#pragma unroll
        for (int w = 1; w < 8; w++) mm = fmaxf(mm, sh_wmax[w]);
        sh_inv = 1.0f / (mm + 1e-5f);
    }
    __syncthreads();
    float inv = sh_inv;

    float4* row = out + (size_t)b * T4;
    int i0 = blockIdx.x * 512 + tid;
    int i1 = i0 + 256;
    bool a0 = (i0 < T4), a1 = (i1 < T4);
    float4 v0, v1;
    if (a0) v0 = row[i0];
    if (a1) v1 = row[i1];
    if (a0) {
        v0.x *= inv; v0.y *= inv; v0.z *= inv; v0.w *= inv;
        row[i0] = v0;
    }
    if (a1) {
        v1.x *= inv; v1.y *= inv; v1.z *= inv; v1.w *= inv;
        row[i1] = v1;
    }
}

extern "C" void kernel_launch(void* const* d_in, const int* in_sizes, int n_in,
                              void* d_out, int out_size) {
    // input order: base_audio, harmonic_dist, noise_bands, adsr, gain, noise
    const float* hd     = (const float*)d_in[1];
    const float* nbands = (const float*)d_in[2];
    const float* adsr   = (const float*)d_in[3];
    const float* gain   = (const float*)d_in[4];
    const float* noise  = (const float*)d_in[5];
    float* out = (float*)d_out;

    ddsp_main<<<MAIN_NB, 256>>>(hd, nbands, adsr, gain, noise, out);
    ddsp_norm<<<dim3(NORM_BPR, NBATCH), 256>>>((float4*)out);
}

// round 9
// speedup vs baseline: 1.0611x; 1.0611x over previous
#include <cuda_runtime.h>
#include <math.h>

#define T_LEN    176400
#define NBATCH   16
#define NHARM    64
#define NBANDS   65
#define MAIN_NB  690          // ceil(176400/256)
#define NORM_BPR 87           // 87*512 = 44544 >= 44100 float4 per row
#define PI_D 3.141592653589793115997963468544185161590576171875

// Scratch (no allocations allowed). Transposed layout [batch][block]:
// norm's reduce reads are coalesced. Every slot overwritten by plain stores
// each call before being read -> no reset needed, replay-deterministic.
__device__ float g_partial[NBATCH * MAIN_NB];

// ---------------------------------------------------------------------------
// Range reduction, bit-exact w.r.t. the reference's f32 argument:
//  n = RNE(arg/2pi) via 1.5*2^23 magic; 2-term Cody-Waite -> r in [-pi,pi]
//  (4 fma-pipe ops), then __sinf(r) on the MUFU pipe (abs err 2^-21.4 on
//  [-pi,pi], verified rel_err 2.6e-7 in R8).
// ---------------------------------------------------------------------------
__device__ __forceinline__ float sin_reduced(float a) {
    const float I2PI  = 0.15915494309189535f;
    const float MAGIC = 12582912.0f;                // 1.5 * 2^23
    const float C1    = 6.28318548202514648437500f; // fl32(2*pi)
    const float C2N   = 1.7484556000744625e-7f;     // -(2*pi - C1)
    float t  = fmaf(a, I2PI, MAGIC);
    float nf = t - MAGIC;                           // RNE(a/2pi), exact int
    float r  = fmaf(nf, -C1, a);
    r = fmaf(nf, C2N, r);                           // r in ~[-pi, pi]
    return __sinf(r);                               // MUFU pipe
}

// ---------------------------------------------------------------------------
// Main kernel: one thread = one time sample, all 16 batches.
// No launch-bounds cap (R8's 64-reg cap spilled), unroll 4 (R8's full unroll
// blew I$/regs). ck comes from a shared table (broadcast LDS, MIO pipe) —
// 21 fma-pipe ops per (i,k). Block max per batch -> plain store (no atomics).
// ---------------------------------------------------------------------------
__global__ void ddsp_main(
    const float* __restrict__ hd,      // (16, 64)
    const float* __restrict__ nbands,  // (16, 65)
    const float* __restrict__ adsr,    // (16, 4)
    const float* __restrict__ gain,    // (16, 1)
    const float* __restrict__ noise,   // (16, T)
    float* __restrict__ out)           // (16, T)
{
    __shared__ float sh_hd[NHARM * 16];   // transposed: [k][b]
    __shared__ float sh_ck[NHARM];
    __shared__ float sh_par[NBATCH * 12];
    __shared__ unsigned int sh_max[NBATCH];

    int tid = threadIdx.x;
    for (int idx = tid; idx < NHARM * 16; idx += 256) {
        int k = idx >> 4, b = idx & 15;
        sh_hd[idx] = hd[b * NHARM + k];
    }
    if (tid < NHARM) {
        const float C32 = (float)(2.0 * PI_D * 440.0);   // fl32(2*pi*440)
        sh_ck[tid] = __fmul_rn(C32, (float)(tid + 1));   // bit-exact ref ck
    }
    if (tid < NBATCH) {
        int b = tid;
        sh_max[b] = 0u;

        float s = 0.0f;
        for (int j = 0; j < NBANDS; j++) s += nbands[b * NBANDS + j];
        float nl = (s / (float)NBANDS) * 0.1f;

        float attack  = adsr[b * 4 + 0];
        float decay   = adsr[b * 4 + 1];
        float sus     = adsr[b * 4 + 2];
        float release = adsr[b * 4 + 3];

        int a  = (int)floorf(__fmul_rn(__fmul_rn(attack,  0.5f), 44100.0f)) + 1;
        int dd = (int)floorf(__fmul_rn(__fmul_rn(decay,   0.5f), 44100.0f)) + 1;
        int rr = (int)floorf(__fmul_rn(__fmul_rn(release, 0.5f), 44100.0f)) + 1;
        int total = a + dd + rr;
        if (total > T_LEN) {
            float scale = __fdiv_rn((float)T_LEN, (float)total);
            a  = (int)floorf(__fmul_rn((float)a,  scale));
            dd = (int)floorf(__fmul_rn((float)dd, scale));
            rr = (int)floorf(__fmul_rn((float)rr, scale));
        }
        int ss = T_LEN - (a + dd + rr);
        if (ss < 0) ss = 0;

        float af = (float)a, df = (float)dd, sf = (float)ss, rf = (float)rr;
        float* P = sh_par + b * 12;
        P[0] = af;
        P[1] = af + df;
        P[2] = af + df + sf;
        P[3] = 1.0f / fmaxf(af - 1.0f, 1.0f);
        P[4] = 1.0f / fmaxf(df - 1.0f, 1.0f);
        P[5] = 1.0f / fmaxf(rf - 1.0f, 1.0f);
        P[6] = sus;
        P[7] = gain[b];
        P[8] = nl;
    }
    __syncthreads();

    int i = blockIdx.x * 256 + tid;
    bool act = (i < T_LEN);
    float fi = (float)i;
    const float DELTA = 4.0f / 176399.0f;         // compile-time IEEE f32
    float ti = __fmul_rn(fi, DELTA);              // jax linspace: iota*delta

    float acc[16];
#pragma unroll
    for (int b = 0; b < 16; b++) acc[b] = 0.0f;

#pragma unroll 4
    for (int k = 0; k < NHARM; k++) {
        float sv = sin_reduced(__fmul_rn(sh_ck[k], ti)); // ref f32 rounding
        const float4* hp = (const float4*)(sh_hd + k * 16);
        float4 h0 = hp[0], h1 = hp[1], h2 = hp[2], h3 = hp[3];
        acc[0]  = fmaf(h0.x, sv, acc[0]);  acc[1]  = fmaf(h0.y, sv, acc[1]);
        acc[2]  = fmaf(h0.z, sv, acc[2]);  acc[3]  = fmaf(h0.w, sv, acc[3]);
        acc[4]  = fmaf(h1.x, sv, acc[4]);  acc[5]  = fmaf(h1.y, sv, acc[5]);
        acc[6]  = fmaf(h1.z, sv, acc[6]);  acc[7]  = fmaf(h1.w, sv, acc[7]);
        acc[8]  = fmaf(h2.x, sv, acc[8]);  acc[9]  = fmaf(h2.y, sv, acc[9]);
        acc[10] = fmaf(h2.z, sv, acc[10]); acc[11] = fmaf(h2.w, sv, acc[11]);
        acc[12] = fmaf(h3.x, sv, acc[12]); acc[13] = fmaf(h3.y, sv, acc[13]);
        acc[14] = fmaf(h3.z, sv, acc[14]); acc[15] = fmaf(h3.w, sv, acc[15]);
    }

    const unsigned full = 0xFFFFFFFFu;
#pragma unroll
    for (int b = 0; b < 16; b++) {
        const float* P = sh_par + b * 12;
        float af = P[0], afd = P[1], ads = P[2];
        float ida = P[3], idd = P[4], idr = P[5];
        float sus = P[6], gn = P[7], nl = P[8];

        float env;
        if (fi < af)       env = fi * ida;
        else if (fi < afd) env = 1.0f + ((sus - 1.0f) * (fi - af)) * idd;
        else if (fi < ads) env = sus;
        else               env = sus * (1.0f - (fi - ads) * idr);

        float nz = act ? noise[b * T_LEN + i] : 0.0f;
        float nn = fmaf(nz, 2.0f, -1.0f) * nl;
        float sig = ((acc[b] + nn) * env) * gn;
        if (!act) sig = 0.0f;
        if (act) out[b * T_LEN + i] = sig;

        float am = fabsf(sig);
#pragma unroll
        for (int off = 16; off; off >>= 1)
            am = fmaxf(am, __shfl_xor_sync(full, am, off));
        if ((tid & 31) == 0) atomicMax(&sh_max[b], __float_as_uint(am));
    }
    __syncthreads();
    // plain stores — transposed [batch][block] slots, overwritten every call
    if (tid < NBATCH)
        g_partial[tid * MAIN_NB + blockIdx.x] = __uint_as_float(sh_max[tid]);
}

// ---------------------------------------------------------------------------
// Norm kernel: block (x, b) redundantly reduces batch b's 690 contiguous
// partials (L2-resident, coalesced), then scales its 2-float4 chunk of row b
// in place. No atomics, no inter-block sync, nothing to reset.
// ---------------------------------------------------------------------------
__global__ void __launch_bounds__(256) ddsp_norm(float4* __restrict__ out) {
    __shared__ float sh_wmax[8];
    __shared__ float sh_inv;
    const int T4 = T_LEN / 4;                 // 44100 float4 per row
    int b = blockIdx.y;
    int tid = threadIdx.x;

    const float* part = g_partial + b * MAIN_NB;
    float m = 0.0f;
    for (int j = tid; j < MAIN_NB; j += 256)
        m = fmaxf(m, part[j]);
    const unsigned full = 0xFFFFFFFFu;
#pragma unroll
    for (int off = 16; off; off >>= 1)
        m = fmaxf(m, __shfl_xor_sync(full, m, off));
    if ((tid & 31) == 0) sh_wmax[tid >> 5] = m;
    __syncthreads();
    if (tid == 0) {
        float mm = sh_wmax[0];
#pragma unroll
        for (int w = 1; w < 8; w++) mm = fmaxf(mm, sh_wmax[w]);
        sh_inv = 1.0f / (mm + 1e-5f);
    }
    __syncthreads();
    float inv = sh_inv;

    float4* row = out + (size_t)b * T4;
    int i0 = blockIdx.x * 512 + tid;
    int i1 = i0 + 256;
    bool a0 = (i0 < T4), a1 = (i1 < T4);
    float4 v0, v1;
    if (a0) v0 = row[i0];
    if (a1) v1 = row[i1];
    if (a0) {
        v0.x *= inv; v0.y *= inv; v0.z *= inv; v0.w *= inv;
        row[i0] = v0;
    }
    if (a1) {
        v1.x *= inv; v1.y *= inv; v1.z *= inv; v1.w *= inv;
        row[i1] = v1;
    }
}

extern "C" void kernel_launch(void* const* d_in, const int* in_sizes, int n_in,
                              void* d_out, int out_size) {
    // input order: base_audio, harmonic_dist, noise_bands, adsr, gain, noise
    const float* hd     = (const float*)d_in[1];
    const float* nbands = (const float*)d_in[2];
    const float* adsr   = (const float*)d_in[3];
    const float* gain   = (const float*)d_in[4];
    const float* noise  = (const float*)d_in[5];
    float* out = (float*)d_out;

    ddsp_main<<<MAIN_NB, 256>>>(hd, nbands, adsr, gain, noise, out);
    ddsp_norm<<<dim3(NORM_BPR, NBATCH), 256>>>((float4*)out);
}